// round 17
// baseline (speedup 1.0000x reference)
#include <cuda_runtime.h>
#include <cuda_fp16.h>

#define NCH 256

// fp16 NHWC copies of the three feature maps.
// offsets (halves): L1=0, L2=33554432, L3=41943040, total 44040192 (88MB)
__device__ __half g_nhwc[44040192];

// ---------------------------------------------------------------------------
// Fused NCHW fp32 -> NHWC fp16 transpose (R12 version, measured 44.7us).
__global__ void __launch_bounds__(256)
nchw_to_nhwc_fused(const float* __restrict__ f1,
                   const float* __restrict__ f2,
                   const float* __restrict__ f3)
{
    __shared__ float tile[64][33];

    int blk = blockIdx.x;
    const float* feat; size_t dst_off; int HW; int t;
    if (blk < 16384)      { feat = f1; dst_off = 0ull;        HW = 65536; t = blk; }
    else if (blk < 20480) { feat = f2; dst_off = 33554432ull; HW = 16384; t = blk - 16384; }
    else                  { feat = f3; dst_off = 41943040ull; HW = 4096;  t = blk - 20480; }

    int nx = HW / 32;
    int cell0 = (t % nx) * 32;
    int rem   = t / nx;
    int c0    = (rem & 3) * 64;
    int b     = rem >> 2;

    int lane = threadIdx.x & 31;
    int wid  = threadIdx.x >> 5;
    const float* src = feat + (size_t)b * NCH * HW;
#pragma unroll
    for (int k = 0; k < 8; k++) {
        int r = wid + k * 8;
        tile[r][lane] = src[(size_t)(c0 + r) * HW + cell0 + lane];
    }
    __syncthreads();
    int cell = threadIdx.x >> 3;
    int c8   = threadIdx.x & 7;
    uint4 u;
    __half2 h;
    h = __floats2half2_rn(tile[c8*8+0][cell], tile[c8*8+1][cell]); u.x = *(unsigned*)&h;
    h = __floats2half2_rn(tile[c8*8+2][cell], tile[c8*8+3][cell]); u.y = *(unsigned*)&h;
    h = __floats2half2_rn(tile[c8*8+4][cell], tile[c8*8+5][cell]); u.z = *(unsigned*)&h;
    h = __floats2half2_rn(tile[c8*8+6][cell], tile[c8*8+7][cell]); u.w = *(unsigned*)&h;
    size_t addr = ((size_t)b * HW + cell0 + cell) * NCH + c0 + c8 * 8;
    reinterpret_cast<uint4*>(g_nhwc + dst_off)[addr >> 3] = u;
}

// ---------------------------------------------------------------------------
// Gather: static separable dedup + SHFL geometry (R16) + BATCHED tap loads:
// the interior fast path loads all 9 window taps into named uint4 registers
// before any FMA -> MLP 9, one scoreboard stall per pixel instead of ~9.

template <int DIM>
__device__ __forceinline__ void axis_weights(float p0, float s1, float bin,
                                             int& base, bool& has4,
                                             float& w0, float& w1,
                                             float& w2, float& w3)
{
    float u0 = fmaf(p0 + 0.25f, bin, s1);
    float u1 = fmaf(p0 + 0.75f, bin, s1);
    float v0 = ((u0 > -1.f) && (u0 < (float)DIM)) ? 0.5f : 0.f;
    float v1 = ((u1 > -1.f) && (u1 < (float)DIM)) ? 0.5f : 0.f;
    float c0 = fminf(fmaxf(u0, 0.f), (float)(DIM - 1));
    float c1 = fminf(fmaxf(u1, 0.f), (float)(DIM - 1));
    int i0 = (int)c0;
    int i1 = (int)c1;
    float l0 = (i0 >= DIM - 1) ? 1.f : c0 - (float)i0;
    float l1 = (i1 >= DIM - 1) ? 1.f : c1 - (float)i1;
    int a0 = min(i0, DIM - 2);
    int a1 = min(i1, DIM - 2);
    int e  = a1 - a0;                       // 0, 1, or 2
    float t00 = (1.f - l0) * v0, t01 = l0 * v0;
    float t10 = (1.f - l1) * v1, t11 = l1 * v1;
    w0 = t00 + ((e == 0) ? t10 : 0.f);
    w1 = t01 + ((e == 0) ? t11 : ((e == 1) ? t10 : 0.f));
    w2 = (e == 1) ? t11 : ((e == 2) ? t10 : 0.f);
    w3 = (e == 2) ? t11 : 0.f;
    base = a0;
    has4 = (e == 2);
}

__device__ __forceinline__ unsigned packh2(float lo, float hi) {
    __half2 h = __floats2half2_rn(lo, hi);
    return *(unsigned*)&h;
}
__device__ __forceinline__ __half2 splat_lo(unsigned u) {
    __half2 h = *(__half2*)&u;
    return __half2half2(__low2half(h));
}
__device__ __forceinline__ __half2 splat_hi(unsigned u) {
    __half2 h = *(__half2*)&u;
    return __half2half2(__high2half(h));
}

// FMA a pre-loaded uint4 tap (v) into q0..q3 with column weight cwh
#define CACC(v, cwh) do {                                                    \
    const __half2* _h = reinterpret_cast<const __half2*>(&(v));              \
    q0 = __hfma2(cwh, _h[0], q0); q1 = __hfma2(cwh, _h[1], q1);              \
    q2 = __hfma2(cwh, _h[2], q2); q3 = __hfma2(cwh, _h[3], q3);              \
} while (0)

#define CTAP(ptr, cwh) do {                                                  \
    uint4 _v = __ldg(reinterpret_cast<const uint4*>(ptr));                   \
    CACC(_v, cwh);                                                           \
} while (0)

#define ROWCOMBINE(rwh) do {                                                 \
    a0 = __hfma2(rwh, q0, a0); a1 = __hfma2(rwh, q1, a1);                    \
    a2 = __hfma2(rwh, q2, a2); a3 = __hfma2(rwh, q3, a3);                    \
} while (0)

template <int P, int H, int W>
__device__ __forceinline__ void gather_level(
    const float* __restrict__ rois, float* __restrict__ out_lvl,
    unsigned lvl_off, float scale, int pxbase, int npx,
    unsigned* __restrict__ sacc)
{
    constexpr int pixels = P * P;
    int tid  = threadIdx.x;
    int wid  = tid >> 5;
    int lane = tid & 31;

    // ---- geometry phase: lane l handles pixel j = l&3 ----
    unsigned g_base, g_rw01, g_rw23, g_cw01, g_cw23, g_flags;
    int g_o2, g_ro1, g_ro2;
    {
        int jl  = lane & 3;
        int pxl = jl * 8 + wid;
        int gpx = pxbase + pxl;
        if (gpx < npx) {
            int n  = gpx / pixels;
            int p  = gpx - n * pixels;
            int ph = p / P;
            int pw = p - ph * P;
            const float* r = rois + n * 5;
            int   bi = (int)r[0];
            float x1 = fmaf(r[1], scale, -0.5f);
            float y1 = fmaf(r[2], scale, -0.5f);
            float bw = (fmaf(r[3], scale, -0.5f) - x1) * (1.0f / (float)P);
            float bh = (fmaf(r[4], scale, -0.5f) - y1) * (1.0f / (float)P);

            int ybase, xbase; bool ry4, cx4;
            float rw0, rw1, rw2, rw3, cw0, cw1, cw2, cw3;
            axis_weights<H>((float)ph, y1, bh, ybase, ry4, rw0, rw1, rw2, rw3);
            axis_weights<W>((float)pw, x1, bw, xbase, cx4, cw0, cw1, cw2, cw3);

            g_base = lvl_off + (unsigned)((bi * H * W + ybase * W + xbase) * NCH);
            g_rw01 = packh2(rw0, rw1); g_rw23 = packh2(rw2, rw3);
            g_cw01 = packh2(cw0, cw1); g_cw23 = packh2(cw2, cw3);
            bool fast = !ry4 && !cx4 && (xbase <= W - 3) && (ybase <= H - 3);
            g_flags = (fast ? 1u : 0u) | (cx4 ? 2u : 0u) | (ry4 ? 4u : 0u);
            g_o2  = (min(xbase + 2, W - 1) - xbase) * NCH;
            g_ro1 = (min(ybase + 1, H - 1) - ybase) * W * NCH;
            g_ro2 = (min(ybase + 2, H - 1) - ybase) * W * NCH;
        } else {
            g_base = lvl_off;        // safe window at level origin
            g_rw01 = g_rw23 = g_cw01 = g_cw23 = 0u;   // all weights 0
            g_flags = 1u;            // fast path
            g_o2 = g_ro1 = g_ro2 = 0;
        }
    }

    __half2 z = __float2half2_rn(0.f);

#pragma unroll
    for (int j = 0; j < 4; j++) {
        unsigned bo   = __shfl_sync(0xffffffffu, g_base,  j);
        unsigned rwp0 = __shfl_sync(0xffffffffu, g_rw01, j);
        unsigned rwp1 = __shfl_sync(0xffffffffu, g_rw23, j);
        unsigned cwp0 = __shfl_sync(0xffffffffu, g_cw01, j);
        unsigned cwp1 = __shfl_sync(0xffffffffu, g_cw23, j);
        unsigned fl   = __shfl_sync(0xffffffffu, g_flags, j);

        __half2 rw0 = splat_lo(rwp0), rw1 = splat_hi(rwp0);
        __half2 rw2 = splat_lo(rwp1), rw3 = splat_hi(rwp1);
        __half2 cw0 = splat_lo(cwp0), cw1 = splat_hi(cwp0);
        __half2 cw2 = splat_lo(cwp1), cw3 = splat_hi(cwp1);

        const __half* rp0 = g_nhwc + bo + lane * 8;
        __half2 a0 = z, a1 = z, a2 = z, a3 = z;

        if (fl & 1u) {
            // interior fast path: ALL 9 loads issued before any FMA (MLP=9)
            const __half* r1 = rp0 + W * NCH;
            const __half* r2 = rp0 + 2 * W * NCH;
            uint4 v00 = __ldg(reinterpret_cast<const uint4*>(rp0));
            uint4 v01 = __ldg(reinterpret_cast<const uint4*>(rp0 + NCH));
            uint4 v02 = __ldg(reinterpret_cast<const uint4*>(rp0 + 2 * NCH));
            uint4 v10 = __ldg(reinterpret_cast<const uint4*>(r1));
            uint4 v11 = __ldg(reinterpret_cast<const uint4*>(r1 + NCH));
            uint4 v12 = __ldg(reinterpret_cast<const uint4*>(r1 + 2 * NCH));
            uint4 v20 = __ldg(reinterpret_cast<const uint4*>(r2));
            uint4 v21 = __ldg(reinterpret_cast<const uint4*>(r2 + NCH));
            uint4 v22 = __ldg(reinterpret_cast<const uint4*>(r2 + 2 * NCH));
            {
                __half2 q0 = z, q1 = z, q2 = z, q3 = z;
                CACC(v00, cw0); CACC(v01, cw1); CACC(v02, cw2);
                ROWCOMBINE(rw0);
            }
            {
                __half2 q0 = z, q1 = z, q2 = z, q3 = z;
                CACC(v10, cw0); CACC(v11, cw1); CACC(v12, cw2);
                ROWCOMBINE(rw1);
            }
            {
                __half2 q0 = z, q1 = z, q2 = z, q3 = z;
                CACC(v20, cw0); CACC(v21, cw1); CACC(v22, cw2);
                ROWCOMBINE(rw2);
            }
        } else {
            int o2  = __shfl_sync(0xffffffffu, g_o2,  j);
            int ro1 = __shfl_sync(0xffffffffu, g_ro1, j);
            int ro2 = __shfl_sync(0xffffffffu, g_ro2, j);
            bool cx4 = (fl & 2u) != 0;
            bool ry4 = (fl & 4u) != 0;
            {
                uint4 u0 = __ldg(reinterpret_cast<const uint4*>(rp0));
                uint4 u1 = __ldg(reinterpret_cast<const uint4*>(rp0 + NCH));
                uint4 u2 = __ldg(reinterpret_cast<const uint4*>(rp0 + o2));
                __half2 q0 = z, q1 = z, q2 = z, q3 = z;
                CACC(u0, cw0); CACC(u1, cw1); CACC(u2, cw2);
                if (cx4) CTAP(rp0 + 3 * NCH, cw3);
                ROWCOMBINE(rw0);
            }
            {
                const __half* rp = rp0 + ro1;
                uint4 u0 = __ldg(reinterpret_cast<const uint4*>(rp));
                uint4 u1 = __ldg(reinterpret_cast<const uint4*>(rp + NCH));
                uint4 u2 = __ldg(reinterpret_cast<const uint4*>(rp + o2));
                __half2 q0 = z, q1 = z, q2 = z, q3 = z;
                CACC(u0, cw0); CACC(u1, cw1); CACC(u2, cw2);
                if (cx4) CTAP(rp + 3 * NCH, cw3);
                ROWCOMBINE(rw1);
            }
            {
                const __half* rp = rp0 + ro2;
                uint4 u0 = __ldg(reinterpret_cast<const uint4*>(rp));
                uint4 u1 = __ldg(reinterpret_cast<const uint4*>(rp + NCH));
                uint4 u2 = __ldg(reinterpret_cast<const uint4*>(rp + o2));
                __half2 q0 = z, q1 = z, q2 = z, q3 = z;
                CACC(u0, cw0); CACC(u1, cw1); CACC(u2, cw2);
                if (cx4) CTAP(rp + 3 * NCH, cw3);
                ROWCOMBINE(rw2);
            }
            if (ry4) {
                const __half* rp = rp0 + 3 * W * NCH;
                uint4 u0 = __ldg(reinterpret_cast<const uint4*>(rp));
                uint4 u1 = __ldg(reinterpret_cast<const uint4*>(rp + NCH));
                uint4 u2 = __ldg(reinterpret_cast<const uint4*>(rp + o2));
                __half2 q0 = z, q1 = z, q2 = z, q3 = z;
                CACC(u0, cw0); CACC(u1, cw1); CACC(u2, cw2);
                if (cx4) CTAP(rp + 3 * NCH, cw3);
                ROWCOMBINE(rw3);
            }
        }

        int pxl = j * 8 + wid;
        int col = pxl ^ lane;
        sacc[(4 * lane + 0) * 32 + col] = *(unsigned*)&a0;
        sacc[(4 * lane + 1) * 32 + col] = *(unsigned*)&a1;
        sacc[(4 * lane + 2) * 32 + col] = *(unsigned*)&a2;
        sacc[(4 * lane + 3) * 32 + col] = *(unsigned*)&a3;
    }
    __syncthreads();

    // store phase: lanes along pixels -> coalesced NCHW writes
    int pxlane = tid & 31;
    int gpx = pxbase + pxlane;
    if (gpx < npx) {
        int n = gpx / pixels;
        int p = gpx - n * pixels;
        float* ob = out_lvl + (size_t)n * NCH * pixels + p;
        int pp0 = (tid >> 5) * 16;
#pragma unroll
        for (int i = 0; i < 16; i++) {
            int pp = pp0 + i;
            unsigned u = sacc[pp * 32 + (pxlane ^ (pp >> 2))];
            __half2 h = *(__half2*)&u;
            int c = 2 * pp;
            ob[(size_t)c       * pixels] = __low2float(h);
            ob[(size_t)(c + 1) * pixels] = __high2float(h);
        }
    }
}

__global__ void __launch_bounds__(256)
roi_gather_kernel(const float* __restrict__ rois, float* __restrict__ out,
                  int N, int nb1, int nb2)
{
    __shared__ unsigned sacc[128 * 32];   // 16KB
    int blk = blockIdx.x;
    if (blk < nb1) {
        gather_level<28, 256, 256>(rois, out, 0u, 0.25f,
                                   blk * 32, N * 784, sacc);
    } else if (blk < nb1 + nb2) {
        float* o2 = out + (size_t)N * NCH * 784;
        gather_level<14, 128, 128>(rois, o2, 33554432u, 0.125f,
                                   (blk - nb1) * 32, N * 196, sacc);
    } else {
        float* o3 = out + (size_t)N * NCH * (784 + 196);
        gather_level<7, 64, 64>(rois, o3, 41943040u, 0.0625f,
                                (blk - nb1 - nb2) * 32, N * 49, sacc);
    }
}

// ---------------------------------------------------------------------------
extern "C" void kernel_launch(void* const* d_in, const int* in_sizes, int n_in,
                              void* d_out, int out_size)
{
    const float* feat1 = (const float*)d_in[0];  // (2,256,256,256)
    const float* feat2 = (const float*)d_in[1];  // (2,256,128,128)
    const float* feat3 = (const float*)d_in[2];  // (2,256,64,64)
    const float* rois  = (const float*)d_in[3];  // (N,5)
    float* out = (float*)d_out;

    const int N = in_sizes[3] / 5;

    // 1) fused transpose: 16384 (L1) + 4096 (L2) + 1024 (L3) blocks
    nchw_to_nhwc_fused<<<21504, 256>>>(feat1, feat2, feat3);

    // 2) fused gather over all three levels
    int nb1 = (N * 784 + 31) / 32;
    int nb2 = (N * 196 + 31) / 32;
    int nb3 = (N * 49  + 31) / 32;
    roi_gather_kernel<<<nb1 + nb2 + nb3, 256>>>(rois, out, N, nb1, nb2);
}